// round 15
// baseline (speedup 1.0000x reference)
#include <cuda_runtime.h>

#define DI __device__ __forceinline__

namespace {
constexpr int Bsz = 2;
constexpr int Nq  = 4096;
constexpr int Nkv = 4096;
constexpr int ENC = 768;
constexpr int DEC = 512;
constexpr int NH  = 8;
constexpr int HD  = 64;
constexpr float SCALE_L2E = 0.125f * 1.4426950408889634f;  // SCALE * log2(e)
}

// Scratch (allocation-free). All f16 tensors stored as packed f16x2 words.
__device__ __align__(16) unsigned g_qh [(size_t)Bsz * NH * Nq  * 32];
__device__ __align__(16) unsigned g_kh [(size_t)Bsz * NH * Nkv * 32];
__device__ __align__(16) unsigned g_vh [(size_t)Bsz * NH * Nkv * 32];
__device__ __align__(16) unsigned g_oh [(size_t)Bsz * Nq * (DEC / 2)];
__device__ __align__(16) unsigned g_xh [(size_t)Bsz * Nq  * (DEC / 2)];
__device__ __align__(16) unsigned g_yh [(size_t)Bsz * Nkv * (ENC / 2)];
__device__ __align__(16) unsigned g_wqh [(size_t)DEC * (DEC / 2)];
__device__ __align__(16) unsigned g_wkvh[(size_t)2 * DEC * (ENC / 2)];
__device__ __align__(16) unsigned g_wph [(size_t)DEC * (DEC / 2)];

DI unsigned packh(float hi, float lo) {    // word = {lo, hi} f16x2
    unsigned r;
    asm("cvt.rn.f16x2.f32 %0, %1, %2;" : "=r"(r) : "f"(hi), "f"(lo));
    return r;
}

DI float ex2(float x) {
    float r;
    asm("ex2.approx.ftz.f32 %0, %1;" : "=f"(r) : "f"(x));
    return r;
}

DI unsigned hex2(unsigned x) {             // ex2 on f16x2 pair
    unsigned r;
    asm("ex2.approx.f16x2 %0, %1;" : "=r"(r) : "r"(x));
    return r;
}

DI void mma_f16(float c[4], unsigned a0, unsigned a1, unsigned a2, unsigned a3,
                unsigned b0, unsigned b1) {
    asm volatile(
        "mma.sync.aligned.m16n8k16.row.col.f32.f16.f16.f32 "
        "{%0,%1,%2,%3}, {%4,%5,%6,%7}, {%8,%9}, {%0,%1,%2,%3};"
        : "+f"(c[0]), "+f"(c[1]), "+f"(c[2]), "+f"(c[3])
        : "r"(a0), "r"(a1), "r"(a2), "r"(a3), "r"(b0), "r"(b1));
}

DI void ldsm4(unsigned& r0, unsigned& r1, unsigned& r2, unsigned& r3, unsigned addr) {
    asm volatile("ldmatrix.sync.aligned.m8n8.x4.shared.b16 {%0,%1,%2,%3}, [%4];"
                 : "=r"(r0), "=r"(r1), "=r"(r2), "=r"(r3) : "r"(addr));
}

DI void ldsm4t(unsigned& r0, unsigned& r1, unsigned& r2, unsigned& r3, unsigned addr) {
    asm volatile("ldmatrix.sync.aligned.m8n8.x4.trans.shared.b16 {%0,%1,%2,%3}, [%4];"
                 : "=r"(r0), "=r"(r1), "=r"(r2), "=r"(r3) : "r"(addr));
}

DI void cp16(unsigned dst, const void* src) {
    asm volatile("cp.async.cg.shared.global [%0], [%1], 16;" :: "r"(dst), "l"(src));
}
DI void cp_commit() { asm volatile("cp.async.commit_group;"); }

// ---------------------------------------------------------------------------
// Fused f32 -> packed f16x2 conversion (single launch, grid-strided cascade)
// ---------------------------------------------------------------------------
namespace {
constexpr int NX4   = Bsz * Nq  * DEC / 4;
constexpr int NY4   = Bsz * Nkv * ENC / 4;
constexpr int NWQ4  = DEC * DEC / 4;
constexpr int NWKV4 = 2 * DEC * ENC / 4;
constexpr int NWP4  = DEC * DEC / 4;
constexpr int NCVT  = NX4 + NY4 + NWQ4 + NWKV4 + NWP4;
}

__global__ void cvt_all(const float4* __restrict__ x, const float4* __restrict__ y,
                        const float4* __restrict__ wq, const float4* __restrict__ wkv,
                        const float4* __restrict__ wp)
{
    int i = blockIdx.x * blockDim.x + threadIdx.x;
    if (i >= NCVT) return;
    const float4* src;
    uint2* dst;
    if (i < NX4)                       { src = x + i;    dst = (uint2*)g_xh + i; }
    else if ((i -= NX4) < NY4)         { src = y + i;    dst = (uint2*)g_yh + i; }
    else if ((i -= NY4) < NWQ4)        { src = wq + i;   dst = (uint2*)g_wqh + i; }
    else if ((i -= NWQ4) < NWKV4)      { src = wkv + i;  dst = (uint2*)g_wkvh + i; }
    else          { i -= NWKV4;          src = wp + i;   dst = (uint2*)g_wph + i; }
    float4 v = *src;
    *dst = uint2{packh(v.y, v.x), packh(v.w, v.z)};
}

// ---------------------------------------------------------------------------
// GEMM-NT, f16 m16n8k16, cp.async double-buffered staging (R14, passing).
// BM=128, BN=128, BK=32. Row stride 20 words. One sync per chunk.
// ---------------------------------------------------------------------------
template<int MODE, int K>
__global__ __launch_bounds__(256, 2) void gemm_mma(float* __restrict__ Cout,
                                                   const float* __restrict__ bias)
{
    constexpr int KW = K / 2;
    __shared__ __align__(16) unsigned As[2][128 * 20];
    __shared__ __align__(16) unsigned Bs[2][128 * 20];

    const int tid  = threadIdx.x;
    const int w    = tid >> 5;
    const int lane = tid & 31;
    const int g    = lane >> 2;
    const int c    = lane & 3;
    const int l7   = lane & 7;
    const int m0   = blockIdx.y << 7;
    const int n0   = blockIdx.x << 7;

    const unsigned* Ah = (MODE == 0) ? g_xh : (MODE == 1) ? g_yh : g_oh;
    const unsigned* Bh = (MODE == 0) ? g_wqh : (MODE == 1) ? g_wkvh : g_wph;

    unsigned aB[2], bB[2];
    #pragma unroll
    for (int p = 0; p < 2; ++p) {
        aB[p] = (unsigned)__cvta_generic_to_shared(&As[p][0]);
        bB[p] = (unsigned)__cvta_generic_to_shared(&Bs[p][0]);
    }

    const int ar0 = tid >> 2, ac0 = tid & 3;
    const int ar1 = (tid + 256) >> 2;
    const unsigned* asrc0 = Ah + (size_t)(m0 + ar0) * KW + ac0 * 4;
    const unsigned* asrc1 = Ah + (size_t)(m0 + ar1) * KW + ac0 * 4;
    const unsigned* bsrc0 = Bh + (size_t)(n0 + ar0) * KW + ac0 * 4;
    const unsigned* bsrc1 = Bh + (size_t)(n0 + ar1) * KW + ac0 * 4;

    cp16(aB[0] + ar0 * 80 + ac0 * 16, asrc0);
    cp16(aB[0] + ar1 * 80 + ac0 * 16, asrc1);
    cp16(bB[0] + ar0 * 80 + ac0 * 16, bsrc0);
    cp16(bB[0] + ar1 * 80 + ac0 * 16, bsrc1);
    cp_commit();

    float acc[16][4] = {};
    constexpr int NIT = K / 32;

    for (int it = 0; it < NIT; ++it) {
        const int p = it & 1;
        asm volatile("cp.async.wait_group 0;" ::: "memory");
        __syncthreads();

        if (it + 1 < NIT) {
            const int kw = (it + 1) * 16;
            cp16(aB[p ^ 1] + ar0 * 80 + ac0 * 16, asrc0 + kw);
            cp16(aB[p ^ 1] + ar1 * 80 + ac0 * 16, asrc1 + kw);
            cp16(bB[p ^ 1] + ar0 * 80 + ac0 * 16, bsrc0 + kw);
            cp16(bB[p ^ 1] + ar1 * 80 + ac0 * 16, bsrc1 + kw);
        }
        cp_commit();

        unsigned a[2][4];
        #pragma unroll
        for (int kk = 0; kk < 2; ++kk) {
            unsigned ad = aB[p] + (unsigned)((w * 16 + ((lane >> 3) & 1) * 8 + l7) * 80
                                             + ((lane >> 4) + kk * 2) * 16);
            ldsm4(a[kk][0], a[kk][1], a[kk][2], a[kk][3], ad);
        }
        #pragma unroll
        for (int j = 0; j < 16; ++j) {
            unsigned bb[4];
            unsigned bd = bB[p] + (unsigned)((j * 8 + l7) * 80 + (lane >> 3) * 16);
            ldsm4(bb[0], bb[1], bb[2], bb[3], bd);
            mma_f16(acc[j], a[0][0], a[0][1], a[0][2], a[0][3], bb[0], bb[1]);
            mma_f16(acc[j], a[1][0], a[1][1], a[1][2], a[1][3], bb[2], bb[3]);
        }
    }

    #pragma unroll
    for (int j = 0; j < 16; ++j) {
        const int n = n0 + j * 8 + 2 * c;
        #pragma unroll
        for (int half = 0; half < 2; ++half) {
            const int m = m0 + w * 16 + g + half * 8;
            float2 val = {acc[j][2 * half], acc[j][2 * half + 1]};
            if (MODE == 0) {
                const int b = m >> 12, nn = m & 4095, h = n >> 6, d = n & 63;
                g_qh[(((size_t)(b * NH + h)) * Nq + nn) * 32 + (d >> 1)] =
                    packh(val.y, val.x);
            } else if (MODE == 1) {
                const int b = m >> 12, nn = m & 4095;
                if (n < DEC) {
                    const int h = n >> 6, d = n & 63;
                    g_kh[(((size_t)(b * NH + h)) * Nkv + nn) * 32 + (d >> 1)] =
                        packh(val.y, val.x);
                } else {
                    const int n2 = n - DEC, h = n2 >> 6, d = n2 & 63;
                    g_vh[(((size_t)(b * NH + h)) * Nkv + nn) * 32 + (d >> 1)] =
                        packh(val.y, val.x);
                }
            } else {
                float2 bb = *(const float2*)&bias[n];
                val.x += bb.x; val.y += bb.y;
                *(float2*)&Cout[(size_t)m * DEC + n] = val;
            }
        }
    }
}

// ---------------------------------------------------------------------------
// Flash attention, f16 mma.m16n8k16, cross-tile software pipelining:
// per iteration: wait+sync -> stage K(t+2)/M(t+2) -> S(t+1) MMA (tensor fills
// the softmax bubble) -> softmax(t) -> PV(t) -> stage V(t+2).
// K 2-slot; V and mask 3-slot (V(t) read after its slot's staging point).
// Arithmetic identical to R14 (same values, same op order) -> same rel_err.
// ---------------------------------------------------------------------------
__global__ __launch_bounds__(256, 2) void attn_kernel(const int* __restrict__ kpm)
{
    constexpr int NT = Nkv / 64;
    __shared__ __align__(16) unsigned Kb[2][64 * 36];
    __shared__ __align__(16) unsigned Vb[3][64 * 36];
    __shared__ __align__(16) int Mb[3][64];

    const int tid  = threadIdx.x;
    const int w    = tid >> 5;
    const int lane = tid & 31;
    const int g    = lane >> 2;
    const int c    = lane & 3;
    const int l7   = lane & 7;
    const int bh   = blockIdx.y;
    const int b    = bh >> 3;
    const int h    = bh & 7;
    const int n0   = blockIdx.x << 7;

    const unsigned* qb = g_qh + ((size_t)bh * Nq + n0) * 32;
    const unsigned* kb = g_kh + (size_t)bh * Nkv * 32;
    const unsigned* vb = g_vh + (size_t)bh * Nkv * 32;
    const int*      mb = kpm + b * Nkv;

    unsigned kS[2], vS[3], mS[3];
    #pragma unroll
    for (int p = 0; p < 2; ++p) kS[p] = (unsigned)__cvta_generic_to_shared(&Kb[p][0]);
    #pragma unroll
    for (int p = 0; p < 3; ++p) {
        vS[p] = (unsigned)__cvta_generic_to_shared(&Vb[p][0]);
        mS[p] = (unsigned)__cvta_generic_to_shared(&Mb[p][0]);
    }

    const unsigned HONE = 0x3C003C00u;   // f16x2 {1.0, 1.0}
    const int srow0  = tid >> 3;
    const int srow1  = srow0 + 32;
    const int scol16 = (tid & 7) * 16;   // smem byte offset
    const int swrd   = (tid & 7) * 4;    // global word offset

    // ---- prologue staging: 4 groups (K0+M0, K1+M1, V0, V1) ----
    cp16(kS[0] + srow0 * 144 + scol16, kb + (size_t)srow0 * 32 + swrd);
    cp16(kS[0] + srow1 * 144 + scol16, kb + (size_t)srow1 * 32 + swrd);
    if (tid < 16) cp16(mS[0] + tid * 16, mb + tid * 4);
    cp_commit();
    cp16(kS[1] + srow0 * 144 + scol16, kb + (size_t)(64 + srow0) * 32 + swrd);
    cp16(kS[1] + srow1 * 144 + scol16, kb + (size_t)(64 + srow1) * 32 + swrd);
    if (tid < 16) cp16(mS[1] + tid * 16, mb + 64 + tid * 4);
    cp_commit();
    cp16(vS[0] + srow0 * 144 + scol16, vb + (size_t)srow0 * 32 + swrd);
    cp16(vS[0] + srow1 * 144 + scol16, vb + (size_t)srow1 * 32 + swrd);
    cp_commit();
    cp16(vS[1] + srow0 * 144 + scol16, vb + (size_t)(64 + srow0) * 32 + swrd);
    cp16(vS[1] + srow1 * 144 + scol16, vb + (size_t)(64 + srow1) * 32 + swrd);
    cp_commit();

    // ---- Q A-frags straight from global (one-time) ----
    unsigned qa[4][4];
    {
        const unsigned* q0 = qb + (size_t)(w * 16 + g) * 32;
        const unsigned* q1 = q0 + 8 * 32;
        #pragma unroll
        for (int kk = 0; kk < 4; ++kk) {
            qa[kk][0] = q0[kk * 8 + c];
            qa[kk][1] = q1[kk * 8 + c];
            qa[kk][2] = q0[kk * 8 + c + 4];
            qa[kk][3] = q1[kk * 8 + c + 4];
        }
    }

    float o[8][4] = {};
    float lacc[4] = {};
    float mr0 = -1e30f, mr1 = -1e30f;
    float sA[8][4], sB[8][4];

    const unsigned krow8 = ((lane >> 3) & 1) * 8 + l7;
    const unsigned jhalf = (lane >> 4);

    auto s_mma = [&](int tt, float (&sn)[8][4]) {
        const unsigned kbp = kS[tt & 1];
        #pragma unroll
        for (int j = 0; j < 8; ++j) {
            unsigned kf[8];
            const unsigned rowad = kbp + (unsigned)((j * 8 + l7) * 144 + (lane >> 3) * 16);
            ldsm4(kf[0], kf[1], kf[2], kf[3], rowad);
            ldsm4(kf[4], kf[5], kf[6], kf[7], rowad + 64);
            sn[j][0] = 0.f; sn[j][1] = 0.f; sn[j][2] = 0.f; sn[j][3] = 0.f;
            #pragma unroll
            for (int kk = 0; kk < 4; ++kk)
                mma_f16(sn[j], qa[kk][0], qa[kk][1], qa[kk][2], qa[kk][3],
                        kf[2 * kk], kf[2 * kk + 1]);
        }
    };

    // S(0) into sA (needs K0 = oldest of 4 groups)
    asm volatile("cp.async.wait_group 3;" ::: "memory");
    __syncthreads();
    s_mma(0, sA);

    auto body = [&](int t, float (&sc)[8][4], float (&sn)[8][4]) {
        // all data except the newest V group is now required
        asm volatile("cp.async.wait_group 1;" ::: "memory");
        __syncthreads();

        // stage K(t+2) + M(t+2) (slot freed: K(t) read last iter, M/V(t-1))
        if (t + 2 < NT) {
            const unsigned kd = kS[t & 1];
            const unsigned* kt = kb + (size_t)(t + 2) * 64 * 32;
            cp16(kd + srow0 * 144 + scol16, kt + (size_t)srow0 * 32 + swrd);
            cp16(kd + srow1 * 144 + scol16, kt + (size_t)srow1 * 32 + swrd);
            if (tid < 16)
                cp16(mS[(t + 2) % 3] + tid * 16, mb + (t + 2) * 64 + tid * 4);
        }
        cp_commit();

        // S(t+1): tensor work in flight while softmax(t) executes below
        if (t + 1 < NT) s_mma(t + 1, sn);

        // ---- softmax(t) on sc ----
        const int* mi = Mb[t % 3];
        float vm0 = -1e30f, vm1 = -1e30f;
        #pragma unroll
        for (int j = 0; j < 8; ++j) {
            const float mk0 = mi[j * 8 + 2 * c]     ? -1e30f : 0.f;
            const float mk1 = mi[j * 8 + 2 * c + 1] ? -1e30f : 0.f;
            sc[j][0] = fmaf(sc[j][0], SCALE_L2E, mk0);
            sc[j][1] = fmaf(sc[j][1], SCALE_L2E, mk1);
            sc[j][2] = fmaf(sc[j][2], SCALE_L2E, mk0);
            sc[j][3] = fmaf(sc[j][3], SCALE_L2E, mk1);
            vm0 = fmaxf(vm0, fmaxf(sc[j][0], sc[j][1]));
            vm1 = fmaxf(vm1, fmaxf(sc[j][2], sc[j][3]));
        }
        vm0 = fmaxf(vm0, __shfl_xor_sync(0xffffffffu, vm0, 1));
        vm0 = fmaxf(vm0, __shfl_xor_sync(0xffffffffu, vm0, 2));
        vm1 = fmaxf(vm1, __shfl_xor_sync(0xffffffffu, vm1, 1));
        vm1 = fmaxf(vm1, __shfl_xor_sync(0xffffffffu, vm1, 2));

        const float mn0 = fmaxf(mr0, vm0);
        const float mn1 = fmaxf(mr1, vm1);
        const float cr0 = ex2(mr0 - mn0);
        const float cr1 = ex2(mr1 - mn1);
        mr0 = mn0; mr1 = mn1;

        #pragma unroll
        for (int j = 0; j < 8; ++j) {
            o[j][0] *= cr0; o[j][1] *= cr0;
            o[j][2] *= cr1; o[j][3] *= cr1;
        }
        lacc[0] *= cr0; lacc[1] *= cr0;
        lacc[2] *= cr1; lacc[3] *= cr1;

        // ---- PV(t): ph streamed per kk ; l += P @ 1 ----
        const unsigned vbp = vS[t % 3];
        #pragma unroll
        for (int kk = 0; kk < 4; ++kk) {
            const unsigned pa0 = hex2(packh(sc[2 * kk][1] - mn0, sc[2 * kk][0] - mn0));
            const unsigned pa1 = hex2(packh(sc[2 * kk][3] - mn1, sc[2 * kk][2] - mn1));
            const unsigned pa2 = hex2(packh(sc[2 * kk + 1][1] - mn0, sc[2 * kk + 1][0] - mn0));
            const unsigned pa3 = hex2(packh(sc[2 * kk + 1][3] - mn1, sc[2 * kk + 1][2] - mn1));
            #pragma unroll
            for (int jp = 0; jp < 8; jp += 2) {
                unsigned b0, b1, b2, b3;
                const unsigned vad = vbp +
                    (unsigned)((16 * kk + krow8) * 144 + (jp + jhalf) * 16);
                ldsm4t(b0, b1, b2, b3, vad);
                mma_f16(o[jp],     pa0, pa1, pa2, pa3, b0, b1);
                mma_f16(o[jp + 1], pa0, pa1, pa2, pa3, b2, b3);
            }
            mma_f16(lacc, pa0, pa1, pa2, pa3, HONE, HONE);
        }

        // stage V(t+2) after all reads of its slot (V(t-1)) and after PV setup
        if (t + 2 < NT) {
            const unsigned vd = vS[(t + 2) % 3];
            const unsigned* vt = vb + (size_t)(t + 2) * 64 * 32;
            cp16(vd + srow0 * 144 + scol16, vt + (size_t)srow0 * 32 + swrd);
            cp16(vd + srow1 * 144 + scol16, vt + (size_t)srow1 * 32 + swrd);
        }
        cp_commit();
    };

    for (int t = 0; t < NT; t += 2) {
        body(t,     sA, sB);
        body(t + 1, sB, sA);
    }

    // ---- normalize + write packed f16 to g_oh [B,N,256 words] ----
    const float inv0 = 1.f / lacc[0];
    const float inv1 = 1.f / lacc[2];
    unsigned* ob = g_oh + ((size_t)(b * Nq) + n0 + w * 16) * 256 + h * 32;
    #pragma unroll
    for (int j = 0; j < 8; ++j) {
        ob[(size_t)g * 256 + j * 4 + c] =
            packh(o[j][1] * inv0, o[j][0] * inv0);
        ob[(size_t)(g + 8) * 256 + j * 4 + c] =
            packh(o[j][3] * inv1, o[j][2] * inv1);
    }
}

// ---------------------------------------------------------------------------
extern "C" void kernel_launch(void* const* d_in, const int* in_sizes, int n_in,
                              void* d_out, int out_size)
{
    (void)in_sizes; (void)n_in; (void)out_size;
    const float* x   = (const float*)d_in[0];
    const float* y   = (const float*)d_in[1];
    const int*   kpm = (const int*)d_in[2];     // bool mask promoted to int32
    const float* Wq  = (const float*)d_in[3];
    const float* Wkv = (const float*)d_in[4];
    const float* Wp  = (const float*)d_in[5];
    const float* bp  = (const float*)d_in[6];
    float* out = (float*)d_out;

    cvt_all<<<(NCVT + 255) / 256, 256>>>((const float4*)x, (const float4*)y,
                                         (const float4*)Wq, (const float4*)Wkv,
                                         (const float4*)Wp);

    gemm_mma<0, DEC><<<dim3(DEC / 128, Bsz * Nq / 128), 256>>>(nullptr, nullptr);
    gemm_mma<1, ENC><<<dim3(2 * DEC / 128, Bsz * Nkv / 128), 256>>>(nullptr, nullptr);
    attn_kernel<<<dim3(Nq / 128, Bsz * NH), 256>>>(kpm);
    gemm_mma<2, DEC><<<dim3(DEC / 128, Bsz * Nq / 128), 256>>>(out, bp);
}

// round 16
// speedup vs baseline: 1.0450x; 1.0450x over previous
#include <cuda_runtime.h>

#define DI __device__ __forceinline__

namespace {
constexpr int Bsz = 2;
constexpr int Nq  = 4096;
constexpr int Nkv = 4096;
constexpr int ENC = 768;
constexpr int DEC = 512;
constexpr int NH  = 8;
constexpr int HD  = 64;
constexpr float SCALE_L2E = 0.125f * 1.4426950408889634f;  // SCALE * log2(e)
}

// Scratch (allocation-free). All f16 tensors stored as packed f16x2 words.
__device__ __align__(16) unsigned g_qh [(size_t)Bsz * NH * Nq  * 32];
__device__ __align__(16) unsigned g_kh [(size_t)Bsz * NH * Nkv * 32];
__device__ __align__(16) unsigned g_vh [(size_t)Bsz * NH * Nkv * 32];
__device__ __align__(16) unsigned g_oh [(size_t)Bsz * Nq * (DEC / 2)];
__device__ __align__(16) unsigned g_xh [(size_t)Bsz * Nq  * (DEC / 2)];
__device__ __align__(16) unsigned g_yh [(size_t)Bsz * Nkv * (ENC / 2)];
__device__ __align__(16) unsigned g_wqh [(size_t)DEC * (DEC / 2)];
__device__ __align__(16) unsigned g_wkvh[(size_t)2 * DEC * (ENC / 2)];
__device__ __align__(16) unsigned g_wph [(size_t)DEC * (DEC / 2)];

DI unsigned packh(float hi, float lo) {    // word = {lo, hi} f16x2
    unsigned r;
    asm("cvt.rn.f16x2.f32 %0, %1, %2;" : "=r"(r) : "f"(hi), "f"(lo));
    return r;
}

DI float ex2(float x) {
    float r;
    asm("ex2.approx.ftz.f32 %0, %1;" : "=f"(r) : "f"(x));
    return r;
}

DI unsigned hex2(unsigned x) {             // ex2 on f16x2 pair
    unsigned r;
    asm("ex2.approx.f16x2 %0, %1;" : "=r"(r) : "r"(x));
    return r;
}

DI void mma_f16(float c[4], unsigned a0, unsigned a1, unsigned a2, unsigned a3,
                unsigned b0, unsigned b1) {
    asm volatile(
        "mma.sync.aligned.m16n8k16.row.col.f32.f16.f16.f32 "
        "{%0,%1,%2,%3}, {%4,%5,%6,%7}, {%8,%9}, {%0,%1,%2,%3};"
        : "+f"(c[0]), "+f"(c[1]), "+f"(c[2]), "+f"(c[3])
        : "r"(a0), "r"(a1), "r"(a2), "r"(a3), "r"(b0), "r"(b1));
}

DI void ldsm4(unsigned& r0, unsigned& r1, unsigned& r2, unsigned& r3, unsigned addr) {
    asm volatile("ldmatrix.sync.aligned.m8n8.x4.shared.b16 {%0,%1,%2,%3}, [%4];"
                 : "=r"(r0), "=r"(r1), "=r"(r2), "=r"(r3) : "r"(addr));
}

DI void ldsm4t(unsigned& r0, unsigned& r1, unsigned& r2, unsigned& r3, unsigned addr) {
    asm volatile("ldmatrix.sync.aligned.m8n8.x4.trans.shared.b16 {%0,%1,%2,%3}, [%4];"
                 : "=r"(r0), "=r"(r1), "=r"(r2), "=r"(r3) : "r"(addr));
}

DI void cp16(unsigned dst, const void* src) {
    asm volatile("cp.async.cg.shared.global [%0], [%1], 16;" :: "r"(dst), "l"(src));
}
DI void cp_commit() { asm volatile("cp.async.commit_group;"); }

// ---------------------------------------------------------------------------
// Fused f32 -> packed f16x2 conversion (single launch)
// ---------------------------------------------------------------------------
namespace {
constexpr int NX4   = Bsz * Nq  * DEC / 4;
constexpr int NY4   = Bsz * Nkv * ENC / 4;
constexpr int NWQ4  = DEC * DEC / 4;
constexpr int NWKV4 = 2 * DEC * ENC / 4;
constexpr int NWP4  = DEC * DEC / 4;
constexpr int NCVT  = NX4 + NY4 + NWQ4 + NWKV4 + NWP4;
}

__global__ void cvt_all(const float4* __restrict__ x, const float4* __restrict__ y,
                        const float4* __restrict__ wq, const float4* __restrict__ wkv,
                        const float4* __restrict__ wp)
{
    int i = blockIdx.x * blockDim.x + threadIdx.x;
    if (i >= NCVT) return;
    const float4* src;
    uint2* dst;
    if (i < NX4)                       { src = x + i;    dst = (uint2*)g_xh + i; }
    else if ((i -= NX4) < NY4)         { src = y + i;    dst = (uint2*)g_yh + i; }
    else if ((i -= NY4) < NWQ4)        { src = wq + i;   dst = (uint2*)g_wqh + i; }
    else if ((i -= NWQ4) < NWKV4)      { src = wkv + i;  dst = (uint2*)g_wkvh + i; }
    else          { i -= NWKV4;          src = wp + i;   dst = (uint2*)g_wph + i; }
    float4 v = *src;
    *dst = uint2{packh(v.y, v.x), packh(v.w, v.z)};
}

// ---------------------------------------------------------------------------
// GEMM-NT, f16 m16n8k16, cp.async double-buffered staging (passing core).
// ---------------------------------------------------------------------------
template<int MODE, int K>
__global__ __launch_bounds__(256, 2) void gemm_mma(float* __restrict__ Cout,
                                                   const float* __restrict__ bias)
{
    constexpr int KW = K / 2;
    __shared__ __align__(16) unsigned As[2][128 * 20];
    __shared__ __align__(16) unsigned Bs[2][128 * 20];

    const int tid  = threadIdx.x;
    const int w    = tid >> 5;
    const int lane = tid & 31;
    const int g    = lane >> 2;
    const int c    = lane & 3;
    const int l7   = lane & 7;
    const int m0   = blockIdx.y << 7;
    const int n0   = blockIdx.x << 7;

    const unsigned* Ah = (MODE == 0) ? g_xh : (MODE == 1) ? g_yh : g_oh;
    const unsigned* Bh = (MODE == 0) ? g_wqh : (MODE == 1) ? g_wkvh : g_wph;

    unsigned aB[2], bB[2];
    #pragma unroll
    for (int p = 0; p < 2; ++p) {
        aB[p] = (unsigned)__cvta_generic_to_shared(&As[p][0]);
        bB[p] = (unsigned)__cvta_generic_to_shared(&Bs[p][0]);
    }

    const int ar0 = tid >> 2, ac0 = tid & 3;
    const int ar1 = (tid + 256) >> 2;
    const unsigned* asrc0 = Ah + (size_t)(m0 + ar0) * KW + ac0 * 4;
    const unsigned* asrc1 = Ah + (size_t)(m0 + ar1) * KW + ac0 * 4;
    const unsigned* bsrc0 = Bh + (size_t)(n0 + ar0) * KW + ac0 * 4;
    const unsigned* bsrc1 = Bh + (size_t)(n0 + ar1) * KW + ac0 * 4;

    cp16(aB[0] + ar0 * 80 + ac0 * 16, asrc0);
    cp16(aB[0] + ar1 * 80 + ac0 * 16, asrc1);
    cp16(bB[0] + ar0 * 80 + ac0 * 16, bsrc0);
    cp16(bB[0] + ar1 * 80 + ac0 * 16, bsrc1);
    cp_commit();

    float acc[16][4] = {};
    constexpr int NIT = K / 32;

    for (int it = 0; it < NIT; ++it) {
        const int p = it & 1;
        asm volatile("cp.async.wait_group 0;" ::: "memory");
        __syncthreads();

        if (it + 1 < NIT) {
            const int kw = (it + 1) * 16;
            cp16(aB[p ^ 1] + ar0 * 80 + ac0 * 16, asrc0 + kw);
            cp16(aB[p ^ 1] + ar1 * 80 + ac0 * 16, asrc1 + kw);
            cp16(bB[p ^ 1] + ar0 * 80 + ac0 * 16, bsrc0 + kw);
            cp16(bB[p ^ 1] + ar1 * 80 + ac0 * 16, bsrc1 + kw);
        }
        cp_commit();

        unsigned a[2][4];
        #pragma unroll
        for (int kk = 0; kk < 2; ++kk) {
            unsigned ad = aB[p] + (unsigned)((w * 16 + ((lane >> 3) & 1) * 8 + l7) * 80
                                             + ((lane >> 4) + kk * 2) * 16);
            ldsm4(a[kk][0], a[kk][1], a[kk][2], a[kk][3], ad);
        }
        #pragma unroll
        for (int j = 0; j < 16; ++j) {
            unsigned bb[4];
            unsigned bd = bB[p] + (unsigned)((j * 8 + l7) * 80 + (lane >> 3) * 16);
            ldsm4(bb[0], bb[1], bb[2], bb[3], bd);
            mma_f16(acc[j], a[0][0], a[0][1], a[0][2], a[0][3], bb[0], bb[1]);
            mma_f16(acc[j], a[1][0], a[1][1], a[1][2], a[1][3], bb[2], bb[3]);
        }
    }

    #pragma unroll
    for (int j = 0; j < 16; ++j) {
        const int n = n0 + j * 8 + 2 * c;
        #pragma unroll
        for (int half = 0; half < 2; ++half) {
            const int m = m0 + w * 16 + g + half * 8;
            float2 val = {acc[j][2 * half], acc[j][2 * half + 1]};
            if (MODE == 0) {
                const int b = m >> 12, nn = m & 4095, h = n >> 6, d = n & 63;
                g_qh[(((size_t)(b * NH + h)) * Nq + nn) * 32 + (d >> 1)] =
                    packh(val.y, val.x);
            } else if (MODE == 1) {
                const int b = m >> 12, nn = m & 4095;
                if (n < DEC) {
                    const int h = n >> 6, d = n & 63;
                    g_kh[(((size_t)(b * NH + h)) * Nkv + nn) * 32 + (d >> 1)] =
                        packh(val.y, val.x);
                } else {
                    const int n2 = n - DEC, h = n2 >> 6, d = n2 & 63;
                    g_vh[(((size_t)(b * NH + h)) * Nkv + nn) * 32 + (d >> 1)] =
                        packh(val.y, val.x);
                }
            } else {
                float2 bb = *(const float2*)&bias[n];
                val.x += bb.x; val.y += bb.y;
                *(float2*)&Cout[(size_t)m * DEC + n] = val;
            }
        }
    }
}

// ---------------------------------------------------------------------------
// Flash attention, f16 mma.m16n8k16, M=32 per warp:
// 128-thread CTA, 4 warps, each warp owns TWO 16-row strips that SHARE every
// K/V B-fragment load -> crossbar bytes per FLOP halved vs R14.
// Schedule = R14 proven single-sync cp.async double buffer.
// Per-strip arithmetic identical to R14 -> rel_err unchanged.
// ---------------------------------------------------------------------------
__global__ __launch_bounds__(128, 2) void attn_kernel(const int* __restrict__ kpm)
{
    constexpr int NT = Nkv / 64;
    __shared__ __align__(16) unsigned KV[2][2][64 * 36];   // [stage][K/V]
    __shared__ __align__(16) int MskI[2][64];

    const int tid  = threadIdx.x;
    const int w    = tid >> 5;          // 0..3
    const int lane = tid & 31;
    const int g    = lane >> 2;
    const int c    = lane & 3;
    const int l7   = lane & 7;
    const int bh   = blockIdx.y;
    const int b    = bh >> 3;
    const int h    = bh & 7;
    const int n0   = blockIdx.x << 7;   // 128-row Q block

    const unsigned* qb = g_qh + ((size_t)bh * Nq + n0) * 32;
    const unsigned* kb = g_kh + (size_t)bh * Nkv * 32;
    const unsigned* vb = g_vh + (size_t)bh * Nkv * 32;
    const int*      mb = kpm + b * Nkv;

    unsigned kB[2], vB[2], mB[2];
    #pragma unroll
    for (int p = 0; p < 2; ++p) {
        kB[p] = (unsigned)__cvta_generic_to_shared(&KV[p][0][0]);
        vB[p] = (unsigned)__cvta_generic_to_shared(&KV[p][1][0]);
        mB[p] = (unsigned)__cvta_generic_to_shared(&MskI[p][0]);
    }
    const unsigned HONE = 0x3C003C00u;   // f16x2 {1.0, 1.0}

    // staging: 512 16B-chunks per matrix, 128 threads -> 4 chunks each
    const int sr   = tid >> 3;          // base row 0..15
    const int sc16 = (tid & 7) * 16;    // smem byte offset within row
    const int swd  = (tid & 7) * 4;     // global word offset within row

    // prologue: stage tile 0
    #pragma unroll
    for (int u = 0; u < 4; ++u) {
        const int r = sr + 16 * u;
        cp16(kB[0] + r * 144 + sc16, kb + (size_t)r * 32 + swd);
        cp16(vB[0] + r * 144 + sc16, vb + (size_t)r * 32 + swd);
    }
    if (tid < 16) cp16(mB[0] + tid * 16, mb + tid * 4);
    cp_commit();

    // Q A-frags straight from global: two strips per warp
    unsigned qa[2][4][4];
    #pragma unroll
    for (int st = 0; st < 2; ++st) {
        const unsigned* q0 = qb + (size_t)(w * 32 + st * 16 + g) * 32;
        const unsigned* q1 = q0 + 8 * 32;
        #pragma unroll
        for (int kk = 0; kk < 4; ++kk) {
            qa[st][kk][0] = q0[kk * 8 + c];
            qa[st][kk][1] = q1[kk * 8 + c];
            qa[st][kk][2] = q0[kk * 8 + c + 4];
            qa[st][kk][3] = q1[kk * 8 + c + 4];
        }
    }

    float o[2][8][4] = {};
    float lacc[2][4] = {};
    float mr[2][2] = {{-1e30f, -1e30f}, {-1e30f, -1e30f}};

    const unsigned krow8 = ((lane >> 3) & 1) * 8 + l7;
    const unsigned jhalf = (lane >> 4);

    for (int it = 0; it < NT; ++it) {
        const int p = it & 1;
        asm volatile("cp.async.wait_group 0;" ::: "memory");
        __syncthreads();

        if (it + 1 < NT) {
            const unsigned* kt = kb + (size_t)(it + 1) * 64 * 32;
            const unsigned* vt = vb + (size_t)(it + 1) * 64 * 32;
            #pragma unroll
            for (int u = 0; u < 4; ++u) {
                const int r = sr + 16 * u;
                cp16(kB[p ^ 1] + r * 144 + sc16, kt + (size_t)r * 32 + swd);
                cp16(vB[p ^ 1] + r * 144 + sc16, vt + (size_t)r * 32 + swd);
            }
            if (tid < 16) cp16(mB[p ^ 1] + tid * 16, mb + (it + 1) * 64 + tid * 4);
        }
        cp_commit();

        // ---- S = Q @ K^T : B-frags shared across both strips ----
        float s[2][8][4];
        #pragma unroll
        for (int j = 0; j < 8; ++j) {
            unsigned kf[8];
            const unsigned rowad = kB[p] + (unsigned)((j * 8 + l7) * 144 + (lane >> 3) * 16);
            ldsm4(kf[0], kf[1], kf[2], kf[3], rowad);
            ldsm4(kf[4], kf[5], kf[6], kf[7], rowad + 64);
            #pragma unroll
            for (int st = 0; st < 2; ++st) {
                s[st][j][0] = 0.f; s[st][j][1] = 0.f;
                s[st][j][2] = 0.f; s[st][j][3] = 0.f;
                #pragma unroll
                for (int kk = 0; kk < 4; ++kk)
                    mma_f16(s[st][j], qa[st][kk][0], qa[st][kk][1],
                            qa[st][kk][2], qa[st][kk][3],
                            kf[2 * kk], kf[2 * kk + 1]);
            }
        }

        // ---- scale(log2) + mask + online softmax, per strip ----
        const int* mi = MskI[p];
        float mn[2][2], cr[2][2];
        {
            float vm[2][2] = {{-1e30f, -1e30f}, {-1e30f, -1e30f}};
            #pragma unroll
            for (int j = 0; j < 8; ++j) {
                const float mk0 = mi[j * 8 + 2 * c]     ? -1e30f : 0.f;
                const float mk1 = mi[j * 8 + 2 * c + 1] ? -1e30f : 0.f;
                #pragma unroll
                for (int st = 0; st < 2; ++st) {
                    s[st][j][0] = fmaf(s[st][j][0], SCALE_L2E, mk0);
                    s[st][j][1] = fmaf(s[st][j][1], SCALE_L2E, mk1);
                    s[st][j][2] = fmaf(s[st][j][2], SCALE_L2E, mk0);
                    s[st][j][3] = fmaf(s[st][j][3], SCALE_L2E, mk1);
                    vm[st][0] = fmaxf(vm[st][0], fmaxf(s[st][j][0], s[st][j][1]));
                    vm[st][1] = fmaxf(vm[st][1], fmaxf(s[st][j][2], s[st][j][3]));
                }
            }
            #pragma unroll
            for (int st = 0; st < 2; ++st) {
                vm[st][0] = fmaxf(vm[st][0], __shfl_xor_sync(0xffffffffu, vm[st][0], 1));
                vm[st][0] = fmaxf(vm[st][0], __shfl_xor_sync(0xffffffffu, vm[st][0], 2));
                vm[st][1] = fmaxf(vm[st][1], __shfl_xor_sync(0xffffffffu, vm[st][1], 1));
                vm[st][1] = fmaxf(vm[st][1], __shfl_xor_sync(0xffffffffu, vm[st][1], 2));
                mn[st][0] = fmaxf(mr[st][0], vm[st][0]);
                mn[st][1] = fmaxf(mr[st][1], vm[st][1]);
                cr[st][0] = ex2(mr[st][0] - mn[st][0]);
                cr[st][1] = ex2(mr[st][1] - mn[st][1]);
                mr[st][0] = mn[st][0];
                mr[st][1] = mn[st][1];
                #pragma unroll
                for (int j = 0; j < 8; ++j) {
                    o[st][j][0] *= cr[st][0]; o[st][j][1] *= cr[st][0];
                    o[st][j][2] *= cr[st][1]; o[st][j][3] *= cr[st][1];
                }
                lacc[st][0] *= cr[st][0]; lacc[st][1] *= cr[st][0];
                lacc[st][2] *= cr[st][1]; lacc[st][3] *= cr[st][1];
            }
        }

        // ---- O += P @ V (V B-frags shared across strips) ; l += P @ 1 ----
        const unsigned vbp = vB[p];
        #pragma unroll
        for (int kk = 0; kk < 4; ++kk) {
            unsigned pa[2][4];
            #pragma unroll
            for (int st = 0; st < 2; ++st) {
                pa[st][0] = hex2(packh(s[st][2 * kk][1] - mn[st][0],
                                       s[st][2 * kk][0] - mn[st][0]));
                pa[st][1] = hex2(packh(s[st][2 * kk][3] - mn[st][1],
                                       s[st][2 * kk][2] - mn[st][1]));
                pa[st][2] = hex2(packh(s[st][2 * kk + 1][1] - mn[st][0],
                                       s[st][2 * kk + 1][0] - mn[st][0]));
                pa[st][3] = hex2(packh(s[st][2 * kk + 1][3] - mn[st][1],
                                       s[st][2 * kk + 1][2] - mn[st][1]));
            }
            #pragma unroll
            for (int jp = 0; jp < 8; jp += 2) {
                unsigned b0, b1, b2, b3;
                const unsigned vad = vbp +
                    (unsigned)((16 * kk + krow8) * 144 + (jp + jhalf) * 16);
                ldsm4t(b0, b1, b2, b3, vad);
                #pragma unroll
                for (int st = 0; st < 2; ++st) {
                    mma_f16(o[st][jp],     pa[st][0], pa[st][1], pa[st][2], pa[st][3], b0, b1);
                    mma_f16(o[st][jp + 1], pa[st][0], pa[st][1], pa[st][2], pa[st][3], b2, b3);
                }
            }
            #pragma unroll
            for (int st = 0; st < 2; ++st)
                mma_f16(lacc[st], pa[st][0], pa[st][1], pa[st][2], pa[st][3], HONE, HONE);
        }
    }

    // ---- normalize + write packed f16 to g_oh [B,N,256 words] ----
    #pragma unroll
    for (int st = 0; st < 2; ++st) {
        const float inv0 = 1.f / lacc[st][0];
        const float inv1 = 1.f / lacc[st][2];
        unsigned* ob = g_oh + ((size_t)(b * Nq) + n0 + w * 32 + st * 16) * 256 + h * 32;
        #pragma unroll
        for (int j = 0; j < 8; ++j) {
            ob[(size_t)g * 256 + j * 4 + c] =
                packh(o[st][j][1] * inv0, o[st][j][0] * inv0);
            ob[(size_t)(g + 8) * 256 + j * 4 + c] =
                packh(o[st][j][3] * inv1, o[st][j][2] * inv1);
        }
    }
}

// ---------------------------------------------------------------------------
extern "C" void kernel_launch(void* const* d_in, const int* in_sizes, int n_in,
                              void* d_out, int out_size)
{
    (void)in_sizes; (void)n_in; (void)out_size;
    const float* x   = (const float*)d_in[0];
    const float* y   = (const float*)d_in[1];
    const int*   kpm = (const int*)d_in[2];     // bool mask promoted to int32
    const float* Wq  = (const float*)d_in[3];
    const float* Wkv = (const float*)d_in[4];
    const float* Wp  = (const float*)d_in[5];
    const float* bp  = (const float*)d_in[6];
    float* out = (float*)d_out;

    cvt_all<<<(NCVT + 255) / 256, 256>>>((const float4*)x, (const float4*)y,
                                         (const float4*)Wq, (const float4*)Wkv,
                                         (const float4*)Wp);

    gemm_mma<0, DEC><<<dim3(DEC / 128, Bsz * Nq / 128), 256>>>(nullptr, nullptr);
    gemm_mma<1, ENC><<<dim3(2 * DEC / 128, Bsz * Nkv / 128), 256>>>(nullptr, nullptr);
    attn_kernel<<<dim3(Nq / 128, Bsz * NH), 128>>>(kpm);
    gemm_mma<2, DEC><<<dim3(DEC / 128, Bsz * Nq / 128), 256>>>(out, bp);
}